// round 1
// baseline (speedup 1.0000x reference)
#include <cuda_runtime.h>
#include <cuda_bf16.h>

#define NTOK 32768
#define DIM  512
#define NEMB 512
#define BM   128      // tokens per block
#define BK   128      // embeddings per k-tile
#define BD   32       // d-slice per smem stage
#define ASTRIDE (BM + 4)   // smem row pad: 4-way (not 8-way) STS conflict, keeps float4 align

__device__ float g_S[NEMB];   // sum over rows i of emb[i][k]^2 (reference's axis=0 quirk)

// ---------------------------------------------------------------------------
// Kernel 1: column sum-of-squares of embeddings  (grid 16, block 256)
// ---------------------------------------------------------------------------
__global__ void col_sumsq_kernel(const float* __restrict__ emb) {
    int c  = blockIdx.x * 32 + (threadIdx.x & 31);
    int r0 = threadIdx.x >> 5;
    float s = 0.f;
    for (int i = r0; i < NEMB; i += 8) {
        float v = emb[i * DIM + c];
        s = fmaf(v, v, s);
    }
    __shared__ float sh[8][32];
    sh[r0][threadIdx.x & 31] = s;
    __syncthreads();
    if (threadIdx.x < 32) {
        float t = 0.f;
        #pragma unroll
        for (int r = 0; r < 8; r++) t += sh[r][threadIdx.x];
        g_S[blockIdx.x * 32 + threadIdx.x] = t;
    }
}

// ---------------------------------------------------------------------------
// Packed fp32x2 helpers (Blackwell FFMA2 — ptxas won't auto-fuse from C++)
// ---------------------------------------------------------------------------
__device__ __forceinline__ unsigned long long dup_f32(float v) {
    unsigned long long r;
    asm("mov.b64 %0, {%1, %1};" : "=l"(r) : "f"(v));
    return r;
}
__device__ __forceinline__ void ffma2(unsigned long long& d,
                                      unsigned long long a, unsigned long long b) {
    asm("fma.rn.f32x2 %0, %1, %2, %0;" : "+l"(d) : "l"(a), "l"(b));
}

// ---------------------------------------------------------------------------
// Kernel 2: fused GEMM + argmin + gather.
// Block: 256 threads, tile 128 tokens x 128 embs per k-tile, 4 k-tiles.
// Thread tile: 8 tokens (as 4 packed f32x2 pairs) x 8 embeddings.
// ---------------------------------------------------------------------------
__global__ __launch_bounds__(256) void vq_kernel(
    const float* __restrict__ x, const float* __restrict__ emb,
    float* __restrict__ out)
{
    __shared__ __align__(16) float As[BD][ASTRIDE];   // [d][token]
    __shared__ __align__(16) float Bs[BD][ASTRIDE];   // [d][emb]
    __shared__ float xn_sm[BM];
    __shared__ int   sidx[BM];

    const int tid  = threadIdx.x;
    const int tx   = tid & 15;   // embedding group (16)
    const int ty   = tid >> 4;   // token group (16)
    const int tok0 = blockIdx.x * BM;

    // --- per-token squared norm: one warp per token, coalesced float4 ---
    {
        int w = tid >> 5, lane = tid & 31;
        for (int t = w; t < BM; t += 8) {
            const float4* px = (const float4*)(x + (size_t)(tok0 + t) * DIM);
            float s = 0.f;
            #pragma unroll
            for (int j = 0; j < 4; j++) {
                float4 v = px[lane + j * 32];
                s = fmaf(v.x, v.x, s); s = fmaf(v.y, v.y, s);
                s = fmaf(v.z, v.z, s); s = fmaf(v.w, v.w, s);
            }
            #pragma unroll
            for (int off = 16; off >= 1; off >>= 1)
                s += __shfl_xor_sync(0xffffffffu, s, off);
            if (lane == 0) xn_sm[t] = s;
        }
    }
    __syncthreads();

    float xnu[8];
    #pragma unroll
    for (int u = 0; u < 8; u++)
        xnu[u] = xn_sm[(u < 4) ? (ty * 4 + u) : (64 + ty * 4 + (u - 4))];

    float bestv[8];
    int   besti[8];
    #pragma unroll
    for (int u = 0; u < 8; u++) { bestv[u] = 3.4e38f; besti[u] = 0; }

    for (int kt = 0; kt < NEMB; kt += BK) {
        unsigned long long acc[4][8];
        #pragma unroll
        for (int p = 0; p < 4; p++)
            #pragma unroll
            for (int v = 0; v < 8; v++) acc[p][v] = 0ull;

        // prefetch stage 0 into registers
        float4 rx[4], re[4];
        #pragma unroll
        for (int i = 0; i < 4; i++) {
            int idx = tid + i * 256;
            int t = idx >> 3, dv = (idx & 7) << 2;
            rx[i] = *(const float4*)(x   + (size_t)(tok0 + t) * DIM + dv);
            re[i] = *(const float4*)(emb + (size_t)(kt   + t) * DIM + dv);
        }

        for (int s = 0; s < DIM / BD; s++) {
            // store current stage (transposed) into smem
            #pragma unroll
            for (int i = 0; i < 4; i++) {
                int idx = tid + i * 256;
                int t = idx >> 3, dv = (idx & 7) << 2;
                As[dv + 0][t] = rx[i].x; As[dv + 1][t] = rx[i].y;
                As[dv + 2][t] = rx[i].z; As[dv + 3][t] = rx[i].w;
                Bs[dv + 0][t] = re[i].x; Bs[dv + 1][t] = re[i].y;
                Bs[dv + 2][t] = re[i].z; Bs[dv + 3][t] = re[i].w;
            }
            __syncthreads();

            // prefetch next stage while computing this one
            if (s + 1 < DIM / BD) {
                int d0 = (s + 1) * BD;
                #pragma unroll
                for (int i = 0; i < 4; i++) {
                    int idx = tid + i * 256;
                    int t = idx >> 3, dv = (idx & 7) << 2;
                    rx[i] = *(const float4*)(x   + (size_t)(tok0 + t) * DIM + d0 + dv);
                    re[i] = *(const float4*)(emb + (size_t)(kt   + t) * DIM + d0 + dv);
                }
            }

            #pragma unroll
            for (int dd = 0; dd < BD; dd++) {
                unsigned long long a2[4];
                const unsigned long long* pa0 =
                    (const unsigned long long*)&As[dd][ty * 4];
                const unsigned long long* pa1 =
                    (const unsigned long long*)&As[dd][64 + ty * 4];
                a2[0] = pa0[0]; a2[1] = pa0[1];
                a2[2] = pa1[0]; a2[3] = pa1[1];
                float4 b0 = *(const float4*)&Bs[dd][tx * 4];
                float4 b1 = *(const float4*)&Bs[dd][64 + tx * 4];
                unsigned long long bb[8];
                bb[0] = dup_f32(b0.x); bb[1] = dup_f32(b0.y);
                bb[2] = dup_f32(b0.z); bb[3] = dup_f32(b0.w);
                bb[4] = dup_f32(b1.x); bb[5] = dup_f32(b1.y);
                bb[6] = dup_f32(b1.z); bb[7] = dup_f32(b1.w);
                #pragma unroll
                for (int p = 0; p < 4; p++)
                    #pragma unroll
                    for (int v = 0; v < 8; v++)
                        ffma2(acc[p][v], a2[p], bb[v]);
            }
            __syncthreads();
        }

        // epilogue: distances with reference-identical rounding, running argmin.
        // v processed in ascending global-index order; strict < keeps first min.
        #pragma unroll
        for (int v = 0; v < 8; v++) {
            int kk = kt + ((v < 4) ? (tx * 4 + v) : (64 + tx * 4 + (v - 4)));
            float Sv = g_S[kk];
            #pragma unroll
            for (int p = 0; p < 4; p++) {
                float lo = __uint_as_float((unsigned)(acc[p][v] & 0xffffffffull));
                float hi = __uint_as_float((unsigned)(acc[p][v] >> 32));
                int ulo = 2 * p, uhi = 2 * p + 1;
                // d = fl( fl(xnorm + S[k]) - 2*sim ):  2*sim is exact, so the
                // fused fma(-2, sim, t1) matches the reference's two-op rounding.
                float t1lo = xnu[ulo] + Sv;
                float t1hi = xnu[uhi] + Sv;
                float dlo = __fmaf_rn(-2.f, lo, t1lo);
                float dhi = __fmaf_rn(-2.f, hi, t1hi);
                if (dlo < bestv[ulo]) { bestv[ulo] = dlo; besti[ulo] = kk; }
                if (dhi < bestv[uhi]) { bestv[uhi] = dhi; besti[uhi] = kk; }
            }
        }
    }

    // cross-thread argmin over the 16 tx lanes (same warp: xor offsets <= 8
    // never cross the 16-lane half-warp); tie -> smaller index (jnp.argmin).
    #pragma unroll
    for (int u = 0; u < 8; u++) {
        float v = bestv[u]; int idx = besti[u];
        #pragma unroll
        for (int off = 8; off >= 1; off >>= 1) {
            float ov = __shfl_xor_sync(0xffffffffu, v, off);
            int   oi = __shfl_xor_sync(0xffffffffu, idx, off);
            if (ov < v || (ov == v && oi < idx)) { v = ov; idx = oi; }
        }
        bestv[u] = v; besti[u] = idx;
    }
    if (tx == 0) {
        #pragma unroll
        for (int u = 0; u < 8; u++) {
            int t = (u < 4) ? (ty * 4 + u) : (64 + ty * 4 + (u - 4));
            sidx[t] = besti[u];
        }
    }
    __syncthreads();

    // fused gather: out[token] = emb[sidx[token]]   (2 tokens per pass,
    // 128 lanes x float4 = one contiguous 2KB row, emb rows L2-hot)
    #pragma unroll 1
    for (int t2 = 0; t2 < BM; t2 += 2) {
        int t     = t2 + (tid >> 7);
        int lane4 = (tid & 127) << 2;
        int k     = sidx[t];
        float4 vv = *(const float4*)(emb + (size_t)k * DIM + lane4);
        *(float4*)(out + (size_t)(tok0 + t) * DIM + lane4) = vv;
    }
}

// ---------------------------------------------------------------------------
extern "C" void kernel_launch(void* const* d_in, const int* in_sizes, int n_in,
                              void* d_out, int out_size) {
    const float* x   = (const float*)d_in[0];   // [32*32*32, 512] fp32
    const float* emb = (const float*)d_in[1];   // [512, 512] fp32
    float* out = (float*)d_out;

    col_sumsq_kernel<<<16, 256>>>(emb);
    vq_kernel<<<NTOK / BM, 256>>>(x, emb, out);
}